// round 13
// baseline (speedup 1.0000x reference)
#include <cuda_runtime.h>
#include <math.h>

#define TSTEPS  2048
#define FDIM    15
#define NGROUPS 8
#define BG      8      // batch rows per group
#define NT      384
#define NCTA    128
#define SPH     260    // padded row stride for h state (floats), 16B-aligned rows
#define WS      260    // padded row stride for weights (floats), 16B-aligned rows
#define RB      148    // red row stride
#define RKC     1188   // red kc stride = 8*RB + 4

typedef unsigned long long u64;

// Double-buffered hidden states (tiny: live in L2)
__device__ float    g_h1[2 * NGROUPS * BG * 256];
__device__ float    g_h2[2 * NGROUPS * BG * 256];
__device__ unsigned g_flags[NCTA];

__global__ void init_kernel() {
    if (threadIdx.x < NCTA) g_flags[threadIdx.x] = 0u;
}

__device__ __forceinline__ float sigmoidf_(float x) {
    return __fdividef(1.0f, 1.0f + __expf(-x));
}

// packed f32x2 fma
__device__ __forceinline__ u64 ffma2(u64 a, u64 b, u64 c) {
    u64 d;
    asm("fma.rn.f32x2 %0, %1, %2, %3;" : "=l"(d) : "l"(a), "l"(b), "l"(c));
    return d;
}

// arrive: block sync, then tid0 fences + publishes epoch to this CTA's flag
__device__ __forceinline__ void bar_arrive(unsigned cta, unsigned e) {
    __syncthreads();
    if (threadIdx.x == 0) {
        __threadfence();
        atomicExch(&g_flags[cta], e);
    }
}
// wait: warp 0 polls all 16 flags of the group (one 64B sector), broadcast via bar
__device__ __forceinline__ void bar_wait(int grp, unsigned e) {
    if (threadIdx.x < 32) {
        int lane = threadIdx.x;
        for (;;) {
            unsigned v = e;
            if (lane < 16) v = ((volatile unsigned*)g_flags)[grp * 16 + lane];
            if (__all_sync(0xffffffffu, v >= e)) break;
        }
        if (lane == 0) __threadfence();
    }
    __syncthreads();
}

__global__ void __launch_bounds__(NT, 1)
gru_kernel(const float* __restrict__ inp, const float* __restrict__ W1,
           const float* __restrict__ U1g, const float* __restrict__ b1,
           const float* __restrict__ W2g, const float* __restrict__ U2g,
           const float* __restrict__ b2, float* __restrict__ out)
{
    extern __shared__ float smem[];
    float* sW    = smem;                  // [144][WS]: 0..47 U1, 48..95 W2, 96..143 U2 (transposed)
    float* sh1   = sW    + 144 * WS;      // [8][SPH]  h1[i-1]
    float* sh2   = sh1   +   8 * SPH;     // [8][SPH]  h2[i-2]
    float* sW1t  = sh2   +   8 * SPH;     // [15][52]  W1 transposed [f][c]
    float* sx    = sW1t  +  15 * 52;      // [8][16]   input row for step i+1
    float* sb    = sx    +   8 * 16;      // [4*48]: b1_in | b1_rec | b2_in | b2_rec
    float* sxp   = sb    +   4 * 48;      // [2][384]  double-buffered xp1 per (g,b,u)
    float* red   = sxp   +   2 * 384;     // [8 kc][8 rows * RB]

    const int tid   = threadIdx.x;
    const int cta   = blockIdx.x;
    const int grp   = cta >> 4;
    const int sl    = cta & 15;
    const int brow0 = grp * BG;

    // ---- one-time: load weight slices (transposed) into SMEM ----
    for (int idx = tid; idx < 48 * 256; idx += NT) {
        int k = idx / 48, c = idx - k * 48;
        int col = ((c >> 4) << 8) + (sl << 4) + (c & 15);   // gate*256 + slice*16 + u
        sW[c * WS + k]          = U1g[k * 768 + col];
        sW[(48 + c) * WS + k]   = W2g[k * 768 + col];
        sW[(96 + c) * WS + k]   = U2g[k * 768 + col];
    }
    for (int idx = tid; idx < 48 * 15; idx += NT) {
        int f = idx / 48, c = idx - f * 48;
        int col = ((c >> 4) << 8) + (sl << 4) + (c & 15);
        sW1t[f * 52 + c] = W1[f * 768 + col];
    }
    for (int c = tid; c < 48; c += NT) {
        int col = ((c >> 4) << 8) + (sl << 4) + (c & 15);
        sb[c]        = b1[col];        // b1_in
        sb[48 + c]   = b1[768 + col];  // b1_rec
        sb[96 + c]   = b2[col];        // b2_in
        sb[144 + c]  = b2[768 + col];  // b2_rec
    }
    if (tid < 128) {
        int b = tid & 7, u = tid >> 3;
        int scol = (sl << 4) + u;
        for (int buf = 0; buf < 2; buf++) {
            g_h1[(buf * NGROUPS + grp) * BG * 256 + b * 256 + scol] = 0.f;
            g_h2[(buf * NGROUPS + grp) * BG * 256 + b * 256 + scol] = 0.f;
        }
    }

    // GEMM decomposition (all 384 threads): kc (k-chunk of 32) x cg (6 cols) x rh (4 rows)
    const int kc  = tid / 48;          // 0..7
    const int r48 = tid - kc * 48;
    const int cg  = r48 >> 1;          // 0..23 (cols cg*6..cg*6+5; cg<16 -> h1, else h2)
    const int rh  = r48 & 1;           // 0..1
    const float* hsel = (cg < 16 ? sh1 : sh2) + rh * 4 * SPH + kc * 32;
    const float* wbse = sW + (cg * 6) * WS + kc * 32;

    const int b15 = tid / 15, f15 = tid - b15 * 15;   // input-load map (tid<120)

    // register-resident own state element
    float hp1 = 0.f;   // valid for tid < 128
    float hp2 = 0.f;   // valid for 128 <= tid < 256

    // stage input row 0
    if (tid < 120)
        sx[b15 * 16 + f15] = __ldg(&inp[(size_t)(brow0 + b15) * (TSTEPS * FDIM) + f15]);

    bar_arrive(cta, 1u);     // __syncthreads inside makes sx/sW1t visible
    bar_wait(grp, 1u);

    // compute xp[0] into sxp buffer 0 (threads 256-383)
    if (tid >= 256) {
        int bu = tid - 256;
        int b = bu & 7, u = bu >> 3;
        #pragma unroll
        for (int g = 0; g < 3; g++) {
            int c = g * 16 + u;
            float a = sb[c];
            const float* xr = sx + b * 16;
            #pragma unroll
            for (int f = 0; f < 15; f++) a += xr[f] * sW1t[f * 52 + c];
            sxp[g * 128 + bu] = a;
        }
    }

    for (int i = 0; i <= TSTEPS; ++i) {
        // ---- prefetch input row i+1 (independent of barrier) ----
        float xin = 0.f;
        if (i + 1 < TSTEPS && tid < 120)
            xin = __ldg(&inp[(size_t)(brow0 + b15) * (TSTEPS * FDIM) + (i + 1) * FDIM + f15]);

        if (i > 0) bar_wait(grp, (unsigned)(i + 1));

        // ---- phase 1: load shared state (L2-coherent) + stage x[i+1] ----
        {
            const float* gh1 = g_h1 + (((i + 1) & 1) * NGROUPS + grp) * BG * 256;  // h1[i-1]
            const float* gh2 = g_h2 + (((i) & 1)     * NGROUPS + grp) * BG * 256;  // h2[i-2]
            for (int idx = tid; idx < 512; idx += NT) {
                int b = idx >> 6, k4 = idx & 63;
                float4 v1 = __ldcg(((const float4*)(gh1 + b * 256)) + k4);
                float4 v2 = __ldcg(((const float4*)(gh2 + b * 256)) + k4);
                *(float4*)(sh1 + b * SPH + (k4 << 2)) = v1;
                *(float4*)(sh2 + b * SPH + (k4 << 2)) = v2;
            }
            if (i + 1 < TSTEPS && tid < 120) sx[b15 * 16 + f15] = xin;
        }
        __syncthreads();

        // ---- phase 2: fused register-tiled GEMM (384 threads, 4x6 tile) ----
        {
            u64 acc[4][6];
            #pragma unroll
            for (int j = 0; j < 4; j++)
                #pragma unroll
                for (int jj = 0; jj < 6; jj++) acc[j][jj] = 0ull;

            #pragma unroll
            for (int s = 0; s < 8; s++) {
                ulonglong2 h2v[4];
                #pragma unroll
                for (int j = 0; j < 4; j++)
                    h2v[j] = *(const ulonglong2*)(hsel + j * SPH + s * 4);
                #pragma unroll
                for (int jj = 0; jj < 6; jj++) {
                    ulonglong2 w2 = *(const ulonglong2*)(wbse + jj * WS + s * 4);
                    #pragma unroll
                    for (int j = 0; j < 4; j++) {
                        acc[j][jj] = ffma2(h2v[j].x, w2.x, acc[j][jj]);
                        acc[j][jj] = ffma2(h2v[j].y, w2.y, acc[j][jj]);
                    }
                }
            }
            #pragma unroll
            for (int j = 0; j < 4; j++) {
                int row = rh * 4 + j;
                #pragma unroll
                for (int jj = 0; jj < 6; jj += 2) {
                    float2 p0 = *(float2*)&acc[j][jj];
                    float2 p1 = *(float2*)&acc[j][jj + 1];
                    *(float2*)&red[kc * RKC + row * RB + cg * 6 + jj] =
                        make_float2(p0.x + p0.y, p1.x + p1.y);
                }
            }
        }
        __syncthreads();

        // ---- phase 3: parallel gates (0-127: L1, 128-255: L2) + xp precompute (256-383) ----
        if (tid < 128) {
            // layer 1: h1[i]
            if (i < TSTEPS) {
                int b = tid & 7, u = tid >> 3;
                int scol = (sl << 4) + u;
                const float* rrow = red + b * RB;
                const float* xps = sxp + (i & 1) * 384;
                float rec[3];
                #pragma unroll
                for (int g = 0; g < 3; g++) {
                    const float* rp = rrow + g * 16 + u;
                    float s01 = rp[0]       + rp[RKC];
                    float s23 = rp[2 * RKC] + rp[3 * RKC];
                    float s45 = rp[4 * RKC] + rp[5 * RKC];
                    float s67 = rp[6 * RKC] + rp[7 * RKC];
                    rec[g] = ((s01 + s23) + (s45 + s67)) + sb[48 + g * 16 + u];
                }
                float z  = sigmoidf_(xps[tid]           + rec[0]);
                float r  = sigmoidf_(xps[128 + tid]     + rec[1]);
                float hh = fmaxf(0.f, xps[256 + tid] + r * rec[2]);
                float hn = z * hp1 + (1.f - z) * hh;
                hp1 = hn;
                g_h1[((i & 1) * NGROUPS + grp) * BG * 256 + b * 256 + scol] = hn;
                if (i == TSTEPS - 1) out[64 * 256 + (brow0 + b) * 256 + scol] = hn;  // state1
            }
        } else if (tid < 256) {
            // layer 2: h2[i-1]
            if (i >= 1) {
                int bu = tid - 128;
                int b = bu & 7, u = bu >> 3;
                int scol = (sl << 4) + u;
                int gb = brow0 + b;
                const float* rrow = red + b * RB;
                float xpv[3], rec[3];
                #pragma unroll
                for (int g = 0; g < 3; g++) {
                    const float* rx = rrow + 48 + g * 16 + u;
                    const float* rr = rrow + 96 + g * 16 + u;
                    float x01 = rx[0]       + rx[RKC];
                    float x23 = rx[2 * RKC] + rx[3 * RKC];
                    float x45 = rx[4 * RKC] + rx[5 * RKC];
                    float x67 = rx[6 * RKC] + rx[7 * RKC];
                    xpv[g] = ((x01 + x23) + (x45 + x67)) + sb[96 + g * 16 + u];
                    float r01 = rr[0]       + rr[RKC];
                    float r23 = rr[2 * RKC] + rr[3 * RKC];
                    float r45 = rr[4 * RKC] + rr[5 * RKC];
                    float r67 = rr[6 * RKC] + rr[7 * RKC];
                    rec[g] = ((r01 + r23) + (r45 + r67)) + sb[144 + g * 16 + u];
                }
                float z  = sigmoidf_(xpv[0] + rec[0]);
                float r  = sigmoidf_(xpv[1] + rec[1]);
                float hh = fmaxf(0.f, xpv[2] + r * rec[2]);
                float hn = z * hp2 + (1.f - z) * hh;
                hp2 = hn;
                g_h2[(((i - 1) & 1) * NGROUPS + grp) * BG * 256 + b * 256 + scol] = hn;
                if (i == TSTEPS) {
                    out[gb * 256 + scol]                = hn;   // x = seq2[:, -1, :]
                    out[2 * 64 * 256 + gb * 256 + scol] = hn;   // state2
                }
            }
        } else {
            // xp precompute for step i+1 (reads sx staged in phase 1)
            if (i + 1 < TSTEPS) {
                int bu = tid - 256;
                int b = bu & 7, u = bu >> 3;
                float* dst = sxp + ((i + 1) & 1) * 384;
                #pragma unroll
                for (int g = 0; g < 3; g++) {
                    int c = g * 16 + u;
                    float a = sb[c];
                    const float* xr = sx + b * 16;
                    #pragma unroll
                    for (int f = 0; f < 15; f++) a += xr[f] * sW1t[f * 52 + c];
                    dst[g * 128 + bu] = a;
                }
            }
        }

        bar_arrive(cta, (unsigned)(i + 2));
    }
}

extern "C" void kernel_launch(void* const* d_in, const int* in_sizes, int n_in,
                              void* d_out, int out_size) {
    const float* inp = (const float*)d_in[0];
    const float* W1  = (const float*)d_in[1];
    const float* U1  = (const float*)d_in[2];
    const float* b1  = (const float*)d_in[3];
    const float* W2  = (const float*)d_in[4];
    const float* U2  = (const float*)d_in[5];
    const float* b2  = (const float*)d_in[6];
    float* out = (float*)d_out;

    size_t smem_bytes = (size_t)(144 * WS + 2 * 8 * SPH +
                                 15 * 52 + 8 * 16 + 4 * 48 + 2 * 384 +
                                 8 * RKC) * sizeof(float);
    cudaFuncSetAttribute(gru_kernel, cudaFuncAttributeMaxDynamicSharedMemorySize,
                         (int)smem_bytes);
    init_kernel<<<1, 128>>>();
    gru_kernel<<<NCTA, NT, smem_bytes>>>(inp, W1, U1, b1, W2, U2, b2, out);
}